// round 2
// baseline (speedup 1.0000x reference)
#include <cuda_runtime.h>
#include <cstdint>

#define CIN 3
#define COUT 16
#define HH 32
#define WW 32
#define OH 30
#define OW 30

// ---- f32x2 packed-math helpers (SASS FFMA2 only reachable via PTX) ----
__device__ __forceinline__ unsigned long long pk2(float a, float b) {
    unsigned long long r;
    asm("mov.b64 %0, {%1, %2};" : "=l"(r) : "f"(a), "f"(b));
    return r;
}
__device__ __forceinline__ unsigned long long fma2(unsigned long long a,
                                                   unsigned long long b,
                                                   unsigned long long c) {
    unsigned long long d;
    asm("fma.rn.f32x2 %0, %1, %2, %3;" : "=l"(d) : "l"(a), "l"(b), "l"(c));
    return d;
}
__device__ __forceinline__ unsigned long long add2(unsigned long long a,
                                                   unsigned long long b) {
    unsigned long long d;
    asm("add.rn.f32x2 %0, %1, %2;" : "=l"(d) : "l"(a), "l"(b));
    return d;
}
__device__ __forceinline__ void upk2(unsigned long long v, float& a, float& b) {
    asm("mov.b64 {%0, %1}, %2;" : "=f"(a), "=f"(b) : "l"(v));
}

// One block = one image. 8 warps; warp w computes channels (2w, 2w+1) packed
// into one f32x2 lane. Lane = output column.
//
// R2: the image lives in shared memory PRE-DUPLICATED ({v,v} 8-byte pairs) so
// every window refill is a single LDS.64 — no pack MOVs in the hot loop.
// The 27-FMA2 chain is split into 3 independent chains (one per input channel)
// to cut the per-row dependency critical path ~3x.
__global__ void __launch_bounds__(256) conv3x3_hswish_kernel(
    const float* __restrict__ x,
    const float* __restrict__ wgt,
    const float* __restrict__ bias,
    float* __restrict__ out)
{
    // dup-pair image: element p of the image is at s_in[p] = {v,v}. 24 KB.
    __shared__ unsigned long long s_in[CIN * HH * WW];

    const int n   = blockIdx.x;
    const int tid = threadIdx.x;

    // Cooperative fill: 768 float4 of input -> 1536 float4 of dup pairs.
    {
        const float4* src = reinterpret_cast<const float4*>(x + (size_t)n * (CIN * HH * WW));
        float4* dst = reinterpret_cast<float4*>(s_in);
        #pragma unroll
        for (int i = 0; i < 3; i++) {
            const int idx = tid + i * 256;
            float4 f = src[idx];
            dst[idx * 2 + 0] = make_float4(f.x, f.x, f.y, f.y);
            dst[idx * 2 + 1] = make_float4(f.z, f.z, f.w, f.w);
        }
    }
    __syncthreads();

    const int warp = tid >> 5;
    const int lane = tid & 31;
    const int c0   = warp * 2;  // channel pair (c0, c0+1)

    // Weights as 27 packed (w_c0, w_c1) pairs; OIHW layout, O-stride = 27.
    unsigned long long wp[27];
    #pragma unroll
    for (int t = 0; t < 27; t++)
        wp[t] = pk2(wgt[c0 * 27 + t], wgt[(c0 + 1) * 27 + t]);
    const unsigned long long bp = pk2(bias[c0], bias[c0 + 1]);

    if (lane >= OW) return;  // all barriers done; safe to retire

    // Rolling window of dup pairs; one LDS.64 each to refill.
    unsigned long long win[3][CIN][3];

    #pragma unroll
    for (int r = 0; r < 2; r++)
        #pragma unroll
        for (int ci = 0; ci < CIN; ci++)
            #pragma unroll
            for (int kx = 0; kx < 3; kx++)
                win[r][ci][kx] = s_in[ci * HH * WW + r * WW + lane + kx];

    float* out0 = out + ((size_t)n * COUT + c0) * (OH * OW) + lane;

    // Period-3 outer loop keeps slot indices compile-time constant.
    #pragma unroll 1
    for (int yb = 0; yb < OH; yb += 3) {
        #pragma unroll
        for (int j = 0; j < 3; j++) {
            const int y    = yb + j;
            const int snew = (j + 2) % 3;
            // bring in input row y+2 (rows 2..31; always in-bounds)
            #pragma unroll
            for (int ci = 0; ci < CIN; ci++)
                #pragma unroll
                for (int kx = 0; kx < 3; kx++)
                    win[snew][ci][kx] = s_in[ci * HH * WW + (y + 2) * WW + lane + kx];

            // 3 independent accumulator chains (one per input channel).
            unsigned long long acc0 = bp, acc1 = 0ULL, acc2 = 0ULL;
            #pragma unroll
            for (int ky = 0; ky < 3; ky++) {
                const int s = (j + ky) % 3;  // compile-time
                #pragma unroll
                for (int kx = 0; kx < 3; kx++) {
                    acc0 = fma2(win[s][0][kx], wp[0 * 9 + ky * 3 + kx], acc0);
                    acc1 = fma2(win[s][1][kx], wp[1 * 9 + ky * 3 + kx], acc1);
                    acc2 = fma2(win[s][2][kx], wp[2 * 9 + ky * 3 + kx], acc2);
                }
            }
            unsigned long long acc = add2(acc0, add2(acc1, acc2));

            float v0, v1;
            upk2(acc, v0, v1);
            // relu(v) * min(v+3, 6) / 6
            float o0 = fmaxf(v0, 0.0f) * fminf(v0 + 3.0f, 6.0f) * (1.0f / 6.0f);
            float o1 = fmaxf(v1, 0.0f) * fminf(v1 + 3.0f, 6.0f) * (1.0f / 6.0f);
            out0[y * OW]           = o0;   // channel c0
            out0[OH * OW + y * OW] = o1;   // channel c0+1
        }
    }
}

extern "C" void kernel_launch(void* const* d_in, const int* in_sizes, int n_in,
                              void* d_out, int out_size) {
    const float* x = (const float*)d_in[0];
    const float* w = (const float*)d_in[1];
    const float* b = (const float*)d_in[2];
    float* out = (float*)d_out;

    const int N = in_sizes[0] / (CIN * HH * WW);  // 4096
    conv3x3_hswish_kernel<<<N, 256>>>(x, w, b, out);
}

// round 3
// speedup vs baseline: 1.2853x; 1.2853x over previous
#include <cuda_runtime.h>
#include <cstdint>

#define CIN 3
#define COUT 16
#define HH 32
#define WW 32
#define OH 30
#define OW 30

typedef unsigned long long u64;

// ---- f32x2 packed-math helpers ----
__device__ __forceinline__ u64 pk2(float a, float b) {
    u64 r;
    asm("mov.b64 %0, {%1, %2};" : "=l"(r) : "f"(a), "f"(b));
    return r;
}
__device__ __forceinline__ u64 dup2(float a) {
    u64 r;
    asm("mov.b64 %0, {%1, %1};" : "=l"(r) : "f"(a));
    return r;
}
__device__ __forceinline__ u64 fma2(u64 a, u64 b, u64 c) {
    u64 d;
    asm("fma.rn.f32x2 %0, %1, %2, %3;" : "=l"(d) : "l"(a), "l"(b), "l"(c));
    return d;
}
__device__ __forceinline__ void upk2(u64 v, float& a, float& b) {
    asm("mov.b64 {%0, %1}, %2;" : "=f"(a), "=f"(b) : "l"(v));
}

// activation: relu(v) * min(v+3,6)/6  ==  max(v,0) * min(v*(1/6)+0.5, 1)
__device__ __forceinline__ float hswish_relu(float v) {
    return fmaxf(v, 0.0f) * fminf(v * (1.0f / 6.0f) + 0.5f, 1.0f);
}

// One block = one image. 8 warps; warp w -> output channels (2w, 2w+1) packed
// in f32x2. Lane = output column (30 active).
//
// Streaming scheme: iterate over INPUT rows r. Row r's 9 window values (3 ci x
// 3 kx) are loaded once (scalar LDS.32) and contribute to the 3 in-flight
// output accumulators (rows r, r-1, r-2 with w[ky=0,1,2]). Row r+1 is
// prefetched a full iteration ahead of use, hiding LDS latency.
__global__ void __launch_bounds__(256, 2) conv3x3_hswish_kernel(
    const float* __restrict__ x,
    const float* __restrict__ wgt,
    const float* __restrict__ bias,
    float* __restrict__ out)
{
    __shared__ float s_in[CIN * HH * WW];  // 12 KB

    const int n   = blockIdx.x;
    const int tid = threadIdx.x;

    {   // coalesced image load: 768 float4 / 256 threads
        const float4* src = reinterpret_cast<const float4*>(x + (size_t)n * (CIN * HH * WW));
        float4* dst = reinterpret_cast<float4*>(s_in);
        #pragma unroll
        for (int i = 0; i < 3; i++) dst[tid + i * 256] = src[tid + i * 256];
    }
    __syncthreads();

    const int warp = tid >> 5;
    const int lane = tid & 31;
    const int c0   = warp * 2;

    // packed weights: wp[ci*9 + ky*3 + kx] = {w[c0], w[c0+1]}
    u64 wp[27];
    #pragma unroll
    for (int t = 0; t < 27; t++)
        wp[t] = pk2(wgt[c0 * 27 + t], wgt[(c0 + 1) * 27 + t]);
    const u64 bp = pk2(bias[c0], bias[c0 + 1]);

    if (lane >= OW) return;  // barriers all done

    const float* base = s_in + lane;          // [ci*1024 + row*32 + kx]
    float* out0 = out + ((size_t)n * COUT + c0) * (OH * OW) + lane;

    u64   cur[9];   // dup pairs of input row r
    float nxt[9];   // scalars of input row r+1 (prefetch)

    // prologue: cur = row 0, nxt = row 1
    #pragma unroll
    for (int ci = 0; ci < CIN; ci++)
        #pragma unroll
        for (int kx = 0; kx < 3; kx++) {
            cur[ci * 3 + kx] = dup2(base[ci * 1024 + 0 * 32 + kx]);
            nxt[ci * 3 + kx] = base[ci * 1024 + 1 * 32 + kx];
        }

    // acc[y % 3] holds the accumulator for output row y
    u64 acc[3];

    // r = 0: start acc for output row 0 (ky=0 weights)
    acc[0] = bp;
    #pragma unroll
    for (int t = 0; t < 9; t++) {
        int ci = t / 3, kx = t % 3;
        acc[0] = fma2(cur[t], wp[ci * 9 + 0 + kx], acc[0]);
    }
    #pragma unroll
    for (int t = 0; t < 9; t++) cur[t] = dup2(nxt[t]);
    #pragma unroll
    for (int ci = 0; ci < CIN; ci++)
        #pragma unroll
        for (int kx = 0; kx < 3; kx++)
            nxt[ci * 3 + kx] = base[ci * 1024 + 2 * 32 + kx];

    // r = 1: acc[0] += ky1, start acc[1] (ky0)
    acc[1] = bp;
    #pragma unroll
    for (int t = 0; t < 9; t++) {
        int ci = t / 3, kx = t % 3;
        acc[0] = fma2(cur[t], wp[ci * 9 + 3 + kx], acc[0]);
        acc[1] = fma2(cur[t], wp[ci * 9 + 0 + kx], acc[1]);
    }
    #pragma unroll
    for (int t = 0; t < 9; t++) cur[t] = dup2(nxt[t]);

    // main: input rows r = 2..28 (27 iterations, 9 groups of 3 so the
    // acc-role indices are compile-time). Each iteration completes output
    // row r-2.
    #pragma unroll 1
    for (int g = 0; g < 9; g++) {
        #pragma unroll
        for (int j = 0; j < 3; j++) {
            const int r  = 2 + g * 3 + j;          // g runtime, j compile-time
            const int iA = j;                       // (r-2)%3
            const int iB = (j + 1) % 3;             // (r-1)%3
            const int iC = (j + 2) % 3;             // r%3

            // prefetch input row r+1 (3..29, always in-bounds)
            #pragma unroll
            for (int ci = 0; ci < CIN; ci++)
                #pragma unroll
                for (int kx = 0; kx < 3; kx++)
                    nxt[ci * 3 + kx] = base[ci * 1024 + (r + 1) * 32 + kx];

            acc[iC] = bp;
            #pragma unroll
            for (int t = 0; t < 9; t++) {
                const int ci = t / 3, kx = t % 3;
                acc[iA] = fma2(cur[t], wp[ci * 9 + 6 + kx], acc[iA]);  // ky=2
                acc[iB] = fma2(cur[t], wp[ci * 9 + 3 + kx], acc[iB]);  // ky=1
                acc[iC] = fma2(cur[t], wp[ci * 9 + 0 + kx], acc[iC]);  // ky=0
            }

            // finish output row y = r-2
            float v0, v1;
            upk2(acc[iA], v0, v1);
            const int yoff = (r - 2) * OW;
            out0[yoff]           = hswish_relu(v0);
            out0[OH * OW + yoff] = hswish_relu(v1);

            #pragma unroll
            for (int t = 0; t < 9; t++) cur[t] = dup2(nxt[t]);
        }
    }

    // epilogue: r = 29, 30, 31 -> finish output rows 27, 28, 29
    // r = 29 (roles: iA=0, iB=1, iC=2); prefetch row 30
    #pragma unroll
    for (int ci = 0; ci < CIN; ci++)
        #pragma unroll
        for (int kx = 0; kx < 3; kx++)
            nxt[ci * 3 + kx] = base[ci * 1024 + 30 * 32 + kx];
    acc[2] = bp;
    #pragma unroll
    for (int t = 0; t < 9; t++) {
        const int ci = t / 3, kx = t % 3;
        acc[0] = fma2(cur[t], wp[ci * 9 + 6 + kx], acc[0]);
        acc[1] = fma2(cur[t], wp[ci * 9 + 3 + kx], acc[1]);
        acc[2] = fma2(cur[t], wp[ci * 9 + 0 + kx], acc[2]);
    }
    {
        float v0, v1; upk2(acc[0], v0, v1);
        out0[27 * OW]           = hswish_relu(v0);
        out0[OH * OW + 27 * OW] = hswish_relu(v1);
    }
    #pragma unroll
    for (int t = 0; t < 9; t++) cur[t] = dup2(nxt[t]);

    // r = 30: load row 31, update acc[1](ky2), acc[2](ky1); finish row 28
    #pragma unroll
    for (int ci = 0; ci < CIN; ci++)
        #pragma unroll
        for (int kx = 0; kx < 3; kx++)
            nxt[ci * 3 + kx] = base[ci * 1024 + 31 * 32 + kx];
    #pragma unroll
    for (int t = 0; t < 9; t++) {
        const int ci = t / 3, kx = t % 3;
        acc[1] = fma2(cur[t], wp[ci * 9 + 6 + kx], acc[1]);
        acc[2] = fma2(cur[t], wp[ci * 9 + 3 + kx], acc[2]);
    }
    {
        float v0, v1; upk2(acc[1], v0, v1);
        out0[28 * OW]           = hswish_relu(v0);
        out0[OH * OW + 28 * OW] = hswish_relu(v1);
    }
    #pragma unroll
    for (int t = 0; t < 9; t++) cur[t] = dup2(nxt[t]);

    // r = 31: acc[2] += ky2; finish row 29
    #pragma unroll
    for (int t = 0; t < 9; t++) {
        const int ci = t / 3, kx = t % 3;
        acc[2] = fma2(cur[t], wp[ci * 9 + 6 + kx], acc[2]);
    }
    {
        float v0, v1; upk2(acc[2], v0, v1);
        out0[29 * OW]           = hswish_relu(v0);
        out0[OH * OW + 29 * OW] = hswish_relu(v1);
    }
}

extern "C" void kernel_launch(void* const* d_in, const int* in_sizes, int n_in,
                              void* d_out, int out_size) {
    const float* x = (const float*)d_in[0];
    const float* w = (const float*)d_in[1];
    const float* b = (const float*)d_in[2];
    float* out = (float*)d_out;

    const int N = in_sizes[0] / (CIN * HH * WW);  // 4096
    conv3x3_hswish_kernel<<<N, 256>>>(x, w, b, out);
}